// round 1
// baseline (speedup 1.0000x reference)
#include <cuda_runtime.h>

// Problem constants
#define BB   4
#define SS   2048
#define DD   1024
#define HH   16
#define DKH  64
#define MM   (BB*SS)   // 8192 rows

// Scratch (allocation-free rule: __device__ globals)
__device__ float g_Q[(size_t)MM*DD];
__device__ float g_K[(size_t)MM*DD];
__device__ float g_V[(size_t)MM*DD];
__device__ float g_C[(size_t)MM*DD];

// ---------------------------------------------------------------------------
// GEMM (NT): C[M,N] = A[M,K] @ W[N,K]^T   (all row-major, y = x @ W.T)
// 128x128 tile, BK=16, 256 threads, 8x8 per thread.
// ---------------------------------------------------------------------------
#define BM  128
#define BN  128
#define BKG 16

__global__ __launch_bounds__(256, 2)
void gemm_nt(const float* __restrict__ A, const float* __restrict__ W,
             float* __restrict__ C, int M, int N, int K)
{
    __shared__ float As[BKG][BM + 4];
    __shared__ float Bs[BKG][BN + 4];

    const int t    = threadIdx.x;
    const int row0 = blockIdx.y * BM;
    const int col0 = blockIdx.x * BN;
    const int tr   = t >> 4;          // 0..15
    const int tc   = t & 15;          // 0..15

    float acc[8][8];
#pragma unroll
    for (int i = 0; i < 8; i++)
#pragma unroll
        for (int j = 0; j < 8; j++) acc[i][j] = 0.0f;

    for (int k0 = 0; k0 < K; k0 += BKG) {
#pragma unroll
        for (int it = 0; it < 2; it++) {
            int slot = t + it * 256;      // 0..511
            int m    = slot >> 2;         // 0..127
            int kv   = (slot & 3) << 2;   // 0,4,8,12
            float4 va = *(const float4*)&A[(size_t)(row0 + m) * K + k0 + kv];
            As[kv + 0][m] = va.x; As[kv + 1][m] = va.y;
            As[kv + 2][m] = va.z; As[kv + 3][m] = va.w;
            float4 vb = *(const float4*)&W[(size_t)(col0 + m) * K + k0 + kv];
            Bs[kv + 0][m] = vb.x; Bs[kv + 1][m] = vb.y;
            Bs[kv + 2][m] = vb.z; Bs[kv + 3][m] = vb.w;
        }
        __syncthreads();

#pragma unroll
        for (int k = 0; k < BKG; k++) {
            float a[8], b[8];
            *(float4*)&a[0] = *(const float4*)&As[k][tr * 8];
            *(float4*)&a[4] = *(const float4*)&As[k][tr * 8 + 4];
            *(float4*)&b[0] = *(const float4*)&Bs[k][tc * 8];
            *(float4*)&b[4] = *(const float4*)&Bs[k][tc * 8 + 4];
#pragma unroll
            for (int i = 0; i < 8; i++)
#pragma unroll
                for (int j = 0; j < 8; j++)
                    acc[i][j] = fmaf(a[i], b[j], acc[i][j]);
        }
        __syncthreads();
    }

#pragma unroll
    for (int i = 0; i < 8; i++) {
        float* cp = &C[(size_t)(row0 + tr * 8 + i) * N + col0 + tc * 8];
        *(float4*)(cp + 0) = make_float4(acc[i][0], acc[i][1], acc[i][2], acc[i][3]);
        *(float4*)(cp + 4) = make_float4(acc[i][4], acc[i][5], acc[i][6], acc[i][7]);
    }
}

// ---------------------------------------------------------------------------
// Causal flash attention, fp32. One q-row per thread, BQ=128 rows per block,
// K/V tiles of 64 in smem (32 KB static). Chunked-online softmax (chunk=8)
// keeps all per-row state in registers with static indexing.
// CTX is written in [b, s, h*dk + i] layout (the reference's transpose-back).
// ---------------------------------------------------------------------------
#define BQ   128
#define BKT  64

__global__ __launch_bounds__(128, 3)
void attn_causal(const float* __restrict__ Q, const float* __restrict__ K,
                 const float* __restrict__ V, float* __restrict__ CTX)
{
    __shared__ float Ks[BKT][DKH];
    __shared__ float Vs[BKT][DKH];

    const int tid = threadIdx.x;
    const int q   = blockIdx.x * BQ + tid;   // this thread's query row
    const int h   = blockIdx.y;
    const int b   = blockIdx.z;

    const float* qptr = Q + ((size_t)(b * SS + q)) * DD + h * DKH;
    float qr[DKH];
#pragma unroll
    for (int i = 0; i < DKH; i += 4) {
        float4 v = *(const float4*)&qptr[i];
        qr[i] = v.x; qr[i + 1] = v.y; qr[i + 2] = v.z; qr[i + 3] = v.w;
    }

    float acc[DKH];
#pragma unroll
    for (int i = 0; i < DKH; i++) acc[i] = 0.0f;
    float m = -1e30f;
    float l = 0.0f;

    const int ktiles = (blockIdx.x * BQ) / BKT + (BQ / BKT);  // causal bound

    for (int kt = 0; kt < ktiles; kt++) {
        const int k0 = kt * BKT;
        __syncthreads();
        // cooperative tile load: 64x64 floats each for K and V
#pragma unroll
        for (int s = 0; s < 8; s++) {
            int slot = tid + s * 128;          // 0..1023
            int r    = slot >> 4;              // 0..63
            int c4   = (slot & 15) << 2;       // 0..60
            size_t grow = ((size_t)(b * SS + k0 + r)) * DD + h * DKH + c4;
            *(float4*)&Ks[r][c4] = *(const float4*)&K[grow];
            *(float4*)&Vs[r][c4] = *(const float4*)&V[grow];
        }
        __syncthreads();

        for (int jc = 0; jc < BKT; jc += 8) {
            float sc[8];
            float cmax = -1e30f;
#pragma unroll
            for (int jj = 0; jj < 8; jj++) {
                const int j = jc + jj;
                float s = 0.0f;
#pragma unroll
                for (int i = 0; i < DKH; i += 4) {
                    float4 kk = *(const float4*)&Ks[j][i];
                    s = fmaf(qr[i + 0], kk.x, s);
                    s = fmaf(qr[i + 1], kk.y, s);
                    s = fmaf(qr[i + 2], kk.z, s);
                    s = fmaf(qr[i + 3], kk.w, s);
                }
                s *= 0.125f;                       // 1/sqrt(64)
                s = (k0 + j > q) ? -1e30f : s;     // causal mask
                sc[jj] = s;
                cmax = fmaxf(cmax, s);
            }
            if (cmax > m) {
                float corr = __expf(m - cmax);
                m = cmax;
                l *= corr;
#pragma unroll
                for (int i = 0; i < DKH; i++) acc[i] *= corr;
            }
#pragma unroll
            for (int jj = 0; jj < 8; jj++) {
                float p = __expf(sc[jj] - m);
                l += p;
#pragma unroll
                for (int i = 0; i < DKH; i += 4) {
                    float4 vv = *(const float4*)&Vs[jc + jj][i];
                    acc[i + 0] = fmaf(p, vv.x, acc[i + 0]);
                    acc[i + 1] = fmaf(p, vv.y, acc[i + 1]);
                    acc[i + 2] = fmaf(p, vv.z, acc[i + 2]);
                    acc[i + 3] = fmaf(p, vv.w, acc[i + 3]);
                }
            }
        }
    }

    const float inv = 1.0f / l;
    float* op = CTX + ((size_t)(b * SS + q)) * DD + h * DKH;
#pragma unroll
    for (int i = 0; i < DKH; i += 4) {
        *(float4*)&op[i] = make_float4(acc[i] * inv, acc[i + 1] * inv,
                                       acc[i + 2] * inv, acc[i + 3] * inv);
    }
}

// ---------------------------------------------------------------------------
// Launch: x,Wq,Wk,Wv,Wo -> out
// ---------------------------------------------------------------------------
extern "C" void kernel_launch(void* const* d_in, const int* in_sizes, int n_in,
                              void* d_out, int out_size)
{
    const float* x  = (const float*)d_in[0];
    const float* Wq = (const float*)d_in[1];
    const float* Wk = (const float*)d_in[2];
    const float* Wv = (const float*)d_in[3];
    const float* Wo = (const float*)d_in[4];
    float* out = (float*)d_out;

    float *Qb, *Kb, *Vb, *Cb;
    cudaGetSymbolAddress((void**)&Qb, g_Q);
    cudaGetSymbolAddress((void**)&Kb, g_K);
    cudaGetSymbolAddress((void**)&Vb, g_V);
    cudaGetSymbolAddress((void**)&Cb, g_C);

    dim3 gg(DD / BN, MM / BM);   // (8, 64)
    gemm_nt<<<gg, 256>>>(x, Wq, Qb, MM, DD, DD);
    gemm_nt<<<gg, 256>>>(x, Wk, Kb, MM, DD, DD);
    gemm_nt<<<gg, 256>>>(x, Wv, Vb, MM, DD, DD);

    dim3 ga(SS / BQ, HH, BB);    // (16, 16, 4)
    attn_causal<<<ga, 128>>>(Qb, Kb, Vb, Cb);

    gemm_nt<<<gg, 256>>>(Cb, Wo, out, MM, DD, DD);
}

// round 2
// speedup vs baseline: 1.3575x; 1.3575x over previous
#include <cuda_runtime.h>

// Problem constants
#define BB   4
#define SS   2048
#define DD   1024
#define HH   16
#define DKH  64
#define MM   (BB*SS)   // 8192 rows

// Scratch (allocation-free rule: __device__ globals)
__device__ float g_Q[(size_t)MM*DD];
__device__ float g_K[(size_t)MM*DD];
__device__ float g_V[(size_t)MM*DD];
__device__ float g_C[(size_t)MM*DD];

// ---------------------------------------------------------------------------
// TF32 tensor-core GEMM (NT): C[M,N] = A[M,K] @ W[N,K]^T (row-major, y=x@W.T)
// 128x128 tile, BK=16, 256 threads (8 warps, 2x4 warp grid, 64x32 per warp).
// mma.sync.aligned.m16n8k8.row.col.f32.tf32.tf32.f32
// smem row stride 136 (== 8 mod 32) -> conflict-free fragment loads.
// ---------------------------------------------------------------------------
#define BM   128
#define BN   128
#define BKG  16
#define SST  136   // smem row stride

__device__ __forceinline__ unsigned f2tf32(float f) {
    unsigned u;
    asm("cvt.rna.tf32.f32 %0, %1;" : "=r"(u) : "f"(f));
    return u;
}

__device__ __forceinline__ void mma_tf32(float c[4], const unsigned a[4], const unsigned b[2]) {
    asm volatile(
        "mma.sync.aligned.m16n8k8.row.col.f32.tf32.tf32.f32 "
        "{%0,%1,%2,%3}, {%4,%5,%6,%7}, {%8,%9}, {%0,%1,%2,%3};\n"
        : "+f"(c[0]), "+f"(c[1]), "+f"(c[2]), "+f"(c[3])
        : "r"(a[0]), "r"(a[1]), "r"(a[2]), "r"(a[3]),
          "r"(b[0]), "r"(b[1]));
}

__global__ __launch_bounds__(256, 2)
void gemm_tf32(const float* __restrict__ A, const float* __restrict__ W,
               float* __restrict__ C, int M, int N, int K)
{
    __shared__ unsigned As[BKG][SST];
    __shared__ unsigned Bs[BKG][SST];

    const int t    = threadIdx.x;
    const int lane = t & 31;
    const int wid  = t >> 5;
    const int wm   = (wid & 1) * 64;   // warp m offset
    const int wn   = (wid >> 1) * 32;  // warp n offset
    const int row0 = blockIdx.y * BM;
    const int col0 = blockIdx.x * BN;

    // gmem loader mapping: slot = t + it*256; m = slot>>2; kv = (slot&3)<<2
    const int lm  = t >> 2;          // 0..63 (base, +64 for it=1)
    const int lkv = (t & 3) << 2;    // 0,4,8,12

    float acc[4][4][4];
#pragma unroll
    for (int i = 0; i < 4; i++)
#pragma unroll
        for (int j = 0; j < 4; j++)
#pragma unroll
            for (int r = 0; r < 4; r++) acc[i][j][r] = 0.0f;

    const int lq = lane & 3;   // k within frag
    const int lg = lane >> 2;  // m/n within frag

    // prefetch first tile
    float4 pa[2], pb[2];
#pragma unroll
    for (int it = 0; it < 2; it++) {
        pa[it] = *(const float4*)&A[(size_t)(row0 + lm + it * 64) * K + lkv];
        pb[it] = *(const float4*)&W[(size_t)(col0 + lm + it * 64) * K + lkv];
    }

    for (int k0 = 0; k0 < K; k0 += BKG) {
        // store current prefetch to smem (tf32-rounded)
#pragma unroll
        for (int it = 0; it < 2; it++) {
            int m = lm + it * 64;
            As[lkv + 0][m] = f2tf32(pa[it].x);
            As[lkv + 1][m] = f2tf32(pa[it].y);
            As[lkv + 2][m] = f2tf32(pa[it].z);
            As[lkv + 3][m] = f2tf32(pa[it].w);
            Bs[lkv + 0][m] = f2tf32(pb[it].x);
            Bs[lkv + 1][m] = f2tf32(pb[it].y);
            Bs[lkv + 2][m] = f2tf32(pb[it].z);
            Bs[lkv + 3][m] = f2tf32(pb[it].w);
        }
        __syncthreads();

        // prefetch next tile
        if (k0 + BKG < K) {
#pragma unroll
            for (int it = 0; it < 2; it++) {
                pa[it] = *(const float4*)&A[(size_t)(row0 + lm + it * 64) * K + k0 + BKG + lkv];
                pb[it] = *(const float4*)&W[(size_t)(col0 + lm + it * 64) * K + k0 + BKG + lkv];
            }
        }

        // two k8 steps
#pragma unroll
        for (int ks = 0; ks < 2; ks++) {
            const int kb = ks * 8;
            unsigned af[4][4], bf[4][2];
#pragma unroll
            for (int mi = 0; mi < 4; mi++) {
                const int mb = wm + mi * 16 + lg;
                af[mi][0] = As[kb + lq][mb];
                af[mi][1] = As[kb + lq][mb + 8];
                af[mi][2] = As[kb + 4 + lq][mb];
                af[mi][3] = As[kb + 4 + lq][mb + 8];
            }
#pragma unroll
            for (int ni = 0; ni < 4; ni++) {
                const int nb = wn + ni * 8 + lg;
                bf[ni][0] = Bs[kb + lq][nb];
                bf[ni][1] = Bs[kb + 4 + lq][nb];
            }
#pragma unroll
            for (int mi = 0; mi < 4; mi++)
#pragma unroll
                for (int ni = 0; ni < 4; ni++)
                    mma_tf32(acc[mi][ni], af[mi], bf[ni]);
        }
        __syncthreads();
    }

    // epilogue
#pragma unroll
    for (int mi = 0; mi < 4; mi++) {
        const int r0 = row0 + wm + mi * 16 + lg;
#pragma unroll
        for (int ni = 0; ni < 4; ni++) {
            const int c0 = col0 + wn + ni * 8 + lq * 2;
            *(float2*)&C[(size_t)r0 * N + c0]       = make_float2(acc[mi][ni][0], acc[mi][ni][1]);
            *(float2*)&C[(size_t)(r0 + 8) * N + c0] = make_float2(acc[mi][ni][2], acc[mi][ni][3]);
        }
    }
}

// ---------------------------------------------------------------------------
// Causal flash attention, fp32 (unchanged from round 0).
// ---------------------------------------------------------------------------
#define BQ   128
#define BKT  64

__global__ __launch_bounds__(128, 3)
void attn_causal(const float* __restrict__ Q, const float* __restrict__ K,
                 const float* __restrict__ V, float* __restrict__ CTX)
{
    __shared__ float Ks[BKT][DKH];
    __shared__ float Vs[BKT][DKH];

    const int tid = threadIdx.x;
    const int q   = blockIdx.x * BQ + tid;
    const int h   = blockIdx.y;
    const int b   = blockIdx.z;

    const float* qptr = Q + ((size_t)(b * SS + q)) * DD + h * DKH;
    float qr[DKH];
#pragma unroll
    for (int i = 0; i < DKH; i += 4) {
        float4 v = *(const float4*)&qptr[i];
        qr[i] = v.x; qr[i + 1] = v.y; qr[i + 2] = v.z; qr[i + 3] = v.w;
    }

    float acc[DKH];
#pragma unroll
    for (int i = 0; i < DKH; i++) acc[i] = 0.0f;
    float m = -1e30f;
    float l = 0.0f;

    const int ktiles = (blockIdx.x * BQ) / BKT + (BQ / BKT);

    for (int kt = 0; kt < ktiles; kt++) {
        const int k0 = kt * BKT;
        __syncthreads();
#pragma unroll
        for (int s = 0; s < 8; s++) {
            int slot = tid + s * 128;
            int r    = slot >> 4;
            int c4   = (slot & 15) << 2;
            size_t grow = ((size_t)(b * SS + k0 + r)) * DD + h * DKH + c4;
            *(float4*)&Ks[r][c4] = *(const float4*)&K[grow];
            *(float4*)&Vs[r][c4] = *(const float4*)&V[grow];
        }
        __syncthreads();

        for (int jc = 0; jc < BKT; jc += 8) {
            float sc[8];
            float cmax = -1e30f;
#pragma unroll
            for (int jj = 0; jj < 8; jj++) {
                const int j = jc + jj;
                float s = 0.0f;
#pragma unroll
                for (int i = 0; i < DKH; i += 4) {
                    float4 kk = *(const float4*)&Ks[j][i];
                    s = fmaf(qr[i + 0], kk.x, s);
                    s = fmaf(qr[i + 1], kk.y, s);
                    s = fmaf(qr[i + 2], kk.z, s);
                    s = fmaf(qr[i + 3], kk.w, s);
                }
                s *= 0.125f;
                s = (k0 + j > q) ? -1e30f : s;
                sc[jj] = s;
                cmax = fmaxf(cmax, s);
            }
            if (cmax > m) {
                float corr = __expf(m - cmax);
                m = cmax;
                l *= corr;
#pragma unroll
                for (int i = 0; i < DKH; i++) acc[i] *= corr;
            }
#pragma unroll
            for (int jj = 0; jj < 8; jj++) {
                float p = __expf(sc[jj] - m);
                l += p;
#pragma unroll
                for (int i = 0; i < DKH; i += 4) {
                    float4 vv = *(const float4*)&Vs[jc + jj][i];
                    acc[i + 0] = fmaf(p, vv.x, acc[i + 0]);
                    acc[i + 1] = fmaf(p, vv.y, acc[i + 1]);
                    acc[i + 2] = fmaf(p, vv.z, acc[i + 2]);
                    acc[i + 3] = fmaf(p, vv.w, acc[i + 3]);
                }
            }
        }
    }

    const float inv = 1.0f / l;
    float* op = CTX + ((size_t)(b * SS + q)) * DD + h * DKH;
#pragma unroll
    for (int i = 0; i < DKH; i += 4) {
        *(float4*)&op[i] = make_float4(acc[i] * inv, acc[i + 1] * inv,
                                       acc[i + 2] * inv, acc[i + 3] * inv);
    }
}

// ---------------------------------------------------------------------------
// Launch
// ---------------------------------------------------------------------------
extern "C" void kernel_launch(void* const* d_in, const int* in_sizes, int n_in,
                              void* d_out, int out_size)
{
    const float* x  = (const float*)d_in[0];
    const float* Wq = (const float*)d_in[1];
    const float* Wk = (const float*)d_in[2];
    const float* Wv = (const float*)d_in[3];
    const float* Wo = (const float*)d_in[4];
    float* out = (float*)d_out;

    float *Qb, *Kb, *Vb, *Cb;
    cudaGetSymbolAddress((void**)&Qb, g_Q);
    cudaGetSymbolAddress((void**)&Kb, g_K);
    cudaGetSymbolAddress((void**)&Vb, g_V);
    cudaGetSymbolAddress((void**)&Cb, g_C);

    dim3 gg(DD / BN, MM / BM);   // (8, 64)
    gemm_tf32<<<gg, 256>>>(x, Wq, Qb, MM, DD, DD);
    gemm_tf32<<<gg, 256>>>(x, Wk, Kb, MM, DD, DD);
    gemm_tf32<<<gg, 256>>>(x, Wv, Vb, MM, DD, DD);

    dim3 ga(SS / BQ, HH, BB);    // (16, 16, 4)
    attn_causal<<<ga, 128>>>(Qb, Kb, Vb, Cb);

    gemm_tf32<<<gg, 256>>>(Cb, Wo, out, MM, DD, DD);
}

// round 4
// speedup vs baseline: 2.4733x; 1.8219x over previous
#include <cuda_runtime.h>
#include <cuda_bf16.h>
#include <cstdint>

// Problem constants
#define BB   4
#define SS   2048
#define DD   1024
#define HH   16
#define DKH  64
#define MM   (BB*SS)   // 8192 rows

// fp32 scratch
__device__ float g_Q[(size_t)MM*DD];
__device__ float g_K[(size_t)MM*DD];
__device__ float g_V[(size_t)MM*DD];
__device__ float g_C[(size_t)MM*DD];

// ---------------------------------------------------------------------------
// TF32 tensor-core GEMM (NT) — unchanged from round 2 (proven).
// ---------------------------------------------------------------------------
#define BM   128
#define BN   128
#define BKG  16
#define SST  136

__device__ __forceinline__ unsigned f2tf32(float f) {
    unsigned u;
    asm("cvt.rna.tf32.f32 %0, %1;" : "=r"(u) : "f"(f));
    return u;
}

__device__ __forceinline__ void mma_tf32(float c[4], const unsigned a[4], const unsigned b[2]) {
    asm volatile(
        "mma.sync.aligned.m16n8k8.row.col.f32.tf32.tf32.f32 "
        "{%0,%1,%2,%3}, {%4,%5,%6,%7}, {%8,%9}, {%0,%1,%2,%3};\n"
        : "+f"(c[0]), "+f"(c[1]), "+f"(c[2]), "+f"(c[3])
        : "r"(a[0]), "r"(a[1]), "r"(a[2]), "r"(a[3]),
          "r"(b[0]), "r"(b[1]));
}

__global__ __launch_bounds__(256, 2)
void gemm_tf32(const float* __restrict__ A, const float* __restrict__ W,
               float* __restrict__ C, int M, int N, int K)
{
    __shared__ unsigned As[BKG][SST];
    __shared__ unsigned Bs[BKG][SST];

    const int t    = threadIdx.x;
    const int lane = t & 31;
    const int wid  = t >> 5;
    const int wm   = (wid & 1) * 64;
    const int wn   = (wid >> 1) * 32;
    const int row0 = blockIdx.y * BM;
    const int col0 = blockIdx.x * BN;

    const int lm  = t >> 2;
    const int lkv = (t & 3) << 2;

    float acc[4][4][4];
#pragma unroll
    for (int i = 0; i < 4; i++)
#pragma unroll
        for (int j = 0; j < 4; j++)
#pragma unroll
            for (int r = 0; r < 4; r++) acc[i][j][r] = 0.0f;

    const int lq = lane & 3;
    const int lg = lane >> 2;

    float4 pa[2], pb[2];
#pragma unroll
    for (int it = 0; it < 2; it++) {
        pa[it] = *(const float4*)&A[(size_t)(row0 + lm + it * 64) * K + lkv];
        pb[it] = *(const float4*)&W[(size_t)(col0 + lm + it * 64) * K + lkv];
    }

    for (int k0 = 0; k0 < K; k0 += BKG) {
#pragma unroll
        for (int it = 0; it < 2; it++) {
            int m = lm + it * 64;
            As[lkv + 0][m] = f2tf32(pa[it].x);
            As[lkv + 1][m] = f2tf32(pa[it].y);
            As[lkv + 2][m] = f2tf32(pa[it].z);
            As[lkv + 3][m] = f2tf32(pa[it].w);
            Bs[lkv + 0][m] = f2tf32(pb[it].x);
            Bs[lkv + 1][m] = f2tf32(pb[it].y);
            Bs[lkv + 2][m] = f2tf32(pb[it].z);
            Bs[lkv + 3][m] = f2tf32(pb[it].w);
        }
        __syncthreads();

        if (k0 + BKG < K) {
#pragma unroll
            for (int it = 0; it < 2; it++) {
                pa[it] = *(const float4*)&A[(size_t)(row0 + lm + it * 64) * K + k0 + BKG + lkv];
                pb[it] = *(const float4*)&W[(size_t)(col0 + lm + it * 64) * K + k0 + BKG + lkv];
            }
        }

#pragma unroll
        for (int ks = 0; ks < 2; ks++) {
            const int kb = ks * 8;
            unsigned af[4][4], bf[4][2];
#pragma unroll
            for (int mi = 0; mi < 4; mi++) {
                const int mb = wm + mi * 16 + lg;
                af[mi][0] = As[kb + lq][mb];
                af[mi][1] = As[kb + lq][mb + 8];
                af[mi][2] = As[kb + 4 + lq][mb];
                af[mi][3] = As[kb + 4 + lq][mb + 8];
            }
#pragma unroll
            for (int ni = 0; ni < 4; ni++) {
                const int nb = wn + ni * 8 + lg;
                bf[ni][0] = Bs[kb + lq][nb];
                bf[ni][1] = Bs[kb + 4 + lq][nb];
            }
#pragma unroll
            for (int mi = 0; mi < 4; mi++)
#pragma unroll
                for (int ni = 0; ni < 4; ni++)
                    mma_tf32(acc[mi][ni], af[mi], bf[ni]);
        }
        __syncthreads();
    }

#pragma unroll
    for (int mi = 0; mi < 4; mi++) {
        const int r0 = row0 + wm + mi * 16 + lg;
#pragma unroll
        for (int ni = 0; ni < 4; ni++) {
            const int c0 = col0 + wn + ni * 8 + lq * 2;
            *(float2*)&C[(size_t)r0 * N + c0]       = make_float2(acc[mi][ni][0], acc[mi][ni][1]);
            *(float2*)&C[(size_t)(r0 + 8) * N + c0] = make_float2(acc[mi][ni][2], acc[mi][ni][3]);
        }
    }
}

// ---------------------------------------------------------------------------
// bf16x3 helpers for attention
// ---------------------------------------------------------------------------
__device__ __forceinline__ void mma_bf16(float c[4], const uint32_t a[4],
                                         uint32_t b0, uint32_t b1) {
    asm volatile(
        "mma.sync.aligned.m16n8k16.row.col.f32.bf16.bf16.f32 "
        "{%0,%1,%2,%3}, {%4,%5,%6,%7}, {%8,%9}, {%0,%1,%2,%3};\n"
        : "+f"(c[0]), "+f"(c[1]), "+f"(c[2]), "+f"(c[3])
        : "r"(a[0]), "r"(a[1]), "r"(a[2]), "r"(a[3]), "r"(b0), "r"(b1));
}

__device__ __forceinline__ uint32_t pkbf(float x, float y) {
    __nv_bfloat162 t = __floats2bfloat162_rn(x, y);
    return *reinterpret_cast<uint32_t*>(&t);
}
// split (x,y) into packed hi + packed lo
__device__ __forceinline__ void split2(float x, float y, uint32_t& hi, uint32_t& lo) {
    __nv_bfloat16 hx = __float2bfloat16(x), hy = __float2bfloat16(y);
    hi = (uint32_t)__bfloat16_as_ushort(hx) | ((uint32_t)__bfloat16_as_ushort(hy) << 16);
    lo = pkbf(x - __bfloat162float(hx), y - __bfloat162float(hy));
}

// ---------------------------------------------------------------------------
// Causal flash attention with bf16x3 mma.sync tensor cores.
// Block = 128 threads (4 warps), q-tile 64 (16 rows/warp), k-tiles of 64.
// K smem row-major [key][d], V smem transposed [d][key]; hi/lo bf16 split.
// Row stride 72 halves -> conflict-free fragment LDS.
// ---------------------------------------------------------------------------
#define KP 72

__global__ __launch_bounds__(128, 3)
void attn_mma(const float* __restrict__ Q, const float* __restrict__ K,
              const float* __restrict__ V, float* __restrict__ CTX)
{
    __shared__ __align__(16) unsigned short Kh[64][KP];
    __shared__ __align__(16) unsigned short Kl[64][KP];
    __shared__ __align__(16) unsigned short Vh[64][KP];   // [d][key]
    __shared__ __align__(16) unsigned short Vl[64][KP];

    const int tid  = threadIdx.x;
    const int lane = tid & 31;
    const int w    = tid >> 5;
    const int g    = lane >> 2;   // 0..7
    const int t4   = lane & 3;    // 0..3
    const int qt   = blockIdx.x;
    const int h    = blockIdx.y;
    const int b    = blockIdx.z;
    const int q0   = qt * 64;
    const int r_lo = q0 + w * 16 + g;
    const int r_hi = r_lo + 8;
    const int hoff = h * DKH;

    // Load this warp's Q fragments (hi/lo) once: rows r_lo/r_hi, 4 k-steps.
    uint32_t qh[4][4], ql[4][4];
#pragma unroll
    for (int c = 0; c < 4; c++) {
        const float* p_lo = &Q[(size_t)(b * SS + r_lo) * DD + hoff + c * 16];
        const float* p_hi = &Q[(size_t)(b * SS + r_hi) * DD + hoff + c * 16];
        float2 v;
        v = *(const float2*)(p_lo + 2 * t4);     split2(v.x, v.y, qh[c][0], ql[c][0]);
        v = *(const float2*)(p_hi + 2 * t4);     split2(v.x, v.y, qh[c][1], ql[c][1]);
        v = *(const float2*)(p_lo + 2 * t4 + 8); split2(v.x, v.y, qh[c][2], ql[c][2]);
        v = *(const float2*)(p_hi + 2 * t4 + 8); split2(v.x, v.y, qh[c][3], ql[c][3]);
    }

    float o[8][4];
#pragma unroll
    for (int j = 0; j < 8; j++)
#pragma unroll
        for (int e = 0; e < 4; e++) o[j][e] = 0.0f;
    float m_lo = -1e30f, m_hi = -1e30f;
    float l_lo = 0.0f,  l_hi = 0.0f;

    for (int kt = 0; kt <= qt; kt++) {
        const int k0 = kt * 64;
        __syncthreads();
        // cooperative load: K tile row-major hi/lo, V tile transposed hi/lo
#pragma unroll
        for (int i = 0; i < 8; i++) {
            int idx = tid + i * 128;           // 0..1023
            int r   = idx >> 4;                // 0..63 (key)
            int c4  = (idx & 15) << 2;         // 0..60 (d)
            const float* gp = &K[(size_t)(b * SS + k0 + r) * DD + hoff + c4];
            float4 v = *(const float4*)gp;
            uint32_t hA, lA, hB, lB;
            split2(v.x, v.y, hA, lA);
            split2(v.z, v.w, hB, lB);
            *(uint32_t*)&Kh[r][c4]     = hA;
            *(uint32_t*)&Kh[r][c4 + 2] = hB;
            *(uint32_t*)&Kl[r][c4]     = lA;
            *(uint32_t*)&Kl[r][c4 + 2] = lB;
            const float* gv = &V[(size_t)(b * SS + k0 + r) * DD + hoff + c4];
            float4 u = *(const float4*)gv;
            __nv_bfloat16 h0 = __float2bfloat16(u.x), h1 = __float2bfloat16(u.y);
            __nv_bfloat16 h2 = __float2bfloat16(u.z), h3 = __float2bfloat16(u.w);
            Vh[c4 + 0][r] = __bfloat16_as_ushort(h0);
            Vh[c4 + 1][r] = __bfloat16_as_ushort(h1);
            Vh[c4 + 2][r] = __bfloat16_as_ushort(h2);
            Vh[c4 + 3][r] = __bfloat16_as_ushort(h3);
            Vl[c4 + 0][r] = __bfloat16_as_ushort(__float2bfloat16(u.x - __bfloat162float(h0)));
            Vl[c4 + 1][r] = __bfloat16_as_ushort(__float2bfloat16(u.y - __bfloat162float(h1)));
            Vl[c4 + 2][r] = __bfloat16_as_ushort(__float2bfloat16(u.z - __bfloat162float(h2)));
            Vl[c4 + 3][r] = __bfloat16_as_ushort(__float2bfloat16(u.w - __bfloat162float(h3)));
        }
        __syncthreads();

        // scores: S[16x64] = Q @ K^T  (bf16x3)
        float s[8][4];
#pragma unroll
        for (int j = 0; j < 8; j++) {
            s[j][0] = s[j][1] = s[j][2] = s[j][3] = 0.0f;
            const int key = 8 * j + g;
#pragma unroll
            for (int c = 0; c < 4; c++) {
                uint32_t bh0 = *(const uint32_t*)&Kh[key][16 * c + 2 * t4];
                uint32_t bh1 = *(const uint32_t*)&Kh[key][16 * c + 2 * t4 + 8];
                uint32_t bl0 = *(const uint32_t*)&Kl[key][16 * c + 2 * t4];
                uint32_t bl1 = *(const uint32_t*)&Kl[key][16 * c + 2 * t4 + 8];
                mma_bf16(s[j], qh[c], bh0, bh1);
                mma_bf16(s[j], qh[c], bl0, bl1);
                mma_bf16(s[j], ql[c], bh0, bh1);
            }
        }

        // scale + causal mask (diagonal tile only)
        const bool diag = (kt == qt);
#pragma unroll
        for (int j = 0; j < 8; j++) {
            const int col = k0 + 8 * j + 2 * t4;
            s[j][0] *= 0.125f; s[j][1] *= 0.125f;
            s[j][2] *= 0.125f; s[j][3] *= 0.125f;
            if (diag) {
                if (col     > r_lo) s[j][0] = -1e30f;
                if (col + 1 > r_lo) s[j][1] = -1e30f;
                if (col     > r_hi) s[j][2] = -1e30f;
                if (col + 1 > r_hi) s[j][3] = -1e30f;
            }
        }

        // row max (per-thread then quad reduce)
        float mx_lo = -1e30f, mx_hi = -1e30f;
#pragma unroll
        for (int j = 0; j < 8; j++) {
            mx_lo = fmaxf(mx_lo, fmaxf(s[j][0], s[j][1]));
            mx_hi = fmaxf(mx_hi, fmaxf(s[j][2], s[j][3]));
        }
        mx_lo = fmaxf(mx_lo, __shfl_xor_sync(0xFFFFFFFF, mx_lo, 1));
        mx_lo = fmaxf(mx_lo, __shfl_xor_sync(0xFFFFFFFF, mx_lo, 2));
        mx_hi = fmaxf(mx_hi, __shfl_xor_sync(0xFFFFFFFF, mx_hi, 1));
        mx_hi = fmaxf(mx_hi, __shfl_xor_sync(0xFFFFFFFF, mx_hi, 2));

        const float mn_lo = fmaxf(m_lo, mx_lo);
        const float mn_hi = fmaxf(m_hi, mx_hi);
        const float cr_lo = __expf(m_lo - mn_lo);
        const float cr_hi = __expf(m_hi - mn_hi);
        m_lo = mn_lo; m_hi = mn_hi;
        l_lo *= cr_lo; l_hi *= cr_hi;
#pragma unroll
        for (int j = 0; j < 8; j++) {
            o[j][0] *= cr_lo; o[j][1] *= cr_lo;
            o[j][2] *= cr_hi; o[j][3] *= cr_hi;
        }

        // p = exp(s - m); split to bf16 hi/lo A-fragments for PV
        uint32_t pah[4][4], pal[4][4];
#pragma unroll
        for (int j = 0; j < 8; j++) {
            float p0 = __expf(s[j][0] - m_lo);
            float p1 = __expf(s[j][1] - m_lo);
            float p2 = __expf(s[j][2] - m_hi);
            float p3 = __expf(s[j][3] - m_hi);
            l_lo += p0 + p1;
            l_hi += p2 + p3;
            uint32_t h01, l01, h23, l23;
            split2(p0, p1, h01, l01);
            split2(p2, p3, h23, l23);
            const int c = j >> 1;
            if ((j & 1) == 0) {
                pah[c][0] = h01; pah[c][1] = h23;
                pal[c][0] = l01; pal[c][1] = l23;
            } else {
                pah[c][2] = h01; pah[c][3] = h23;
                pal[c][2] = l01; pal[c][3] = l23;
            }
        }

        // O += P @ V (bf16x3), V transposed in smem
#pragma unroll
        for (int j = 0; j < 8; j++) {
            const int d = 8 * j + g;
#pragma unroll
            for (int c = 0; c < 4; c++) {
                uint32_t bh0 = *(const uint32_t*)&Vh[d][16 * c + 2 * t4];
                uint32_t bh1 = *(const uint32_t*)&Vh[d][16 * c + 2 * t4 + 8];
                uint32_t bl0 = *(const uint32_t*)&Vl[d][16 * c + 2 * t4];
                uint32_t bl1 = *(const uint32_t*)&Vl[d][16 * c + 2 * t4 + 8];
                mma_bf16(o[j], pah[c], bh0, bh1);
                mma_bf16(o[j], pah[c], bl0, bl1);
                mma_bf16(o[j], pal[c], bh0, bh1);
            }
        }
    }

    // finalize: quad-reduce l, normalize, store
    l_lo += __shfl_xor_sync(0xFFFFFFFF, l_lo, 1);
    l_lo += __shfl_xor_sync(0xFFFFFFFF, l_lo, 2);
    l_hi += __shfl_xor_sync(0xFFFFFFFF, l_hi, 1);
    l_hi += __shfl_xor_sync(0xFFFFFFFF, l_hi, 2);
    const float inv_lo = 1.0f / l_lo;
    const float inv_hi = 1.0f / l_hi;

#pragma unroll
    for (int j = 0; j < 8; j++) {
        const int col = hoff + 8 * j + 2 * t4;
        *(float2*)&CTX[(size_t)(b * SS + r_lo) * DD + col] =
            make_float2(o[j][0] * inv_lo, o[j][1] * inv_lo);
        *(float2*)&CTX[(size_t)(b * SS + r_hi) * DD + col] =
            make_float2(o[j][2] * inv_hi, o[j][3] * inv_hi);
    }
}

// ---------------------------------------------------------------------------
// Launch
// ---------------------------------------------------------------------------
extern "C" void kernel_launch(void* const* d_in, const int* in_sizes, int n_in,
                              void* d_out, int out_size)
{
    const float* x  = (const float*)d_in[0];
    const float* Wq = (const float*)d_in[1];
    const float* Wk = (const float*)d_in[2];
    const float* Wv = (const float*)d_in[3];
    const float* Wo = (const float*)d_in[4];
    float* out = (float*)d_out;

    float *Qb, *Kb, *Vb, *Cb;
    cudaGetSymbolAddress((void**)&Qb, g_Q);
    cudaGetSymbolAddress((void**)&Kb, g_K);
    cudaGetSymbolAddress((void**)&Vb, g_V);
    cudaGetSymbolAddress((void**)&Cb, g_C);

    dim3 gg(DD / BN, MM / BM);   // (8, 64)
    gemm_tf32<<<gg, 256>>>(x, Wq, Qb, MM, DD, DD);
    gemm_tf32<<<gg, 256>>>(x, Wk, Kb, MM, DD, DD);
    gemm_tf32<<<gg, 256>>>(x, Wv, Vb, MM, DD, DD);

    dim3 ga(SS / 64, HH, BB);    // (32, 16, 4)
    attn_mma<<<ga, 128>>>(Qb, Kb, Vb, Cb);

    gemm_tf32<<<gg, 256>>>(Cb, Wo, out, MM, DD, DD);
}

// round 5
// speedup vs baseline: 2.9381x; 1.1880x over previous
#include <cuda_runtime.h>
#include <cuda_bf16.h>
#include <cstdint>

// Problem constants
#define BB   4
#define SS   2048
#define DD   1024
#define HH   16
#define DKH  64
#define MM   (BB*SS)   // 8192 rows

// bf16 hi/lo scratch for Q,K,V ; fp32 context
__device__ __align__(16) __nv_bfloat16 g_qh[(size_t)MM*DD];
__device__ __align__(16) __nv_bfloat16 g_ql[(size_t)MM*DD];
__device__ __align__(16) __nv_bfloat16 g_kh[(size_t)MM*DD];
__device__ __align__(16) __nv_bfloat16 g_kl[(size_t)MM*DD];
__device__ __align__(16) __nv_bfloat16 g_vh[(size_t)MM*DD];
__device__ __align__(16) __nv_bfloat16 g_vl[(size_t)MM*DD];
__device__ float g_C[(size_t)MM*DD];

// ---------------------------------------------------------------------------
// helpers
// ---------------------------------------------------------------------------
__device__ __forceinline__ unsigned f2tf32(float f) {
    unsigned u;
    asm("cvt.rna.tf32.f32 %0, %1;" : "=r"(u) : "f"(f));
    return u;
}
__device__ __forceinline__ void mma_tf32(float c[4], const unsigned a[4], const unsigned b[2]) {
    asm volatile(
        "mma.sync.aligned.m16n8k8.row.col.f32.tf32.tf32.f32 "
        "{%0,%1,%2,%3}, {%4,%5,%6,%7}, {%8,%9}, {%0,%1,%2,%3};\n"
        : "+f"(c[0]), "+f"(c[1]), "+f"(c[2]), "+f"(c[3])
        : "r"(a[0]), "r"(a[1]), "r"(a[2]), "r"(a[3]), "r"(b[0]), "r"(b[1]));
}
__device__ __forceinline__ void mma_bf16(float c[4], const uint32_t a[4],
                                         uint32_t b0, uint32_t b1) {
    asm volatile(
        "mma.sync.aligned.m16n8k16.row.col.f32.bf16.bf16.f32 "
        "{%0,%1,%2,%3}, {%4,%5,%6,%7}, {%8,%9}, {%0,%1,%2,%3};\n"
        : "+f"(c[0]), "+f"(c[1]), "+f"(c[2]), "+f"(c[3])
        : "r"(a[0]), "r"(a[1]), "r"(a[2]), "r"(a[3]), "r"(b0), "r"(b1));
}
__device__ __forceinline__ uint32_t pkbf(float x, float y) {
    __nv_bfloat162 t = __floats2bfloat162_rn(x, y);
    return *reinterpret_cast<uint32_t*>(&t);
}
__device__ __forceinline__ void split2(float x, float y, uint32_t& hi, uint32_t& lo) {
    __nv_bfloat16 hx = __float2bfloat16(x), hy = __float2bfloat16(y);
    hi = (uint32_t)__bfloat16_as_ushort(hx) | ((uint32_t)__bfloat16_as_ushort(hy) << 16);
    lo = pkbf(x - __bfloat162float(hx), y - __bfloat162float(hy));
}
__device__ __forceinline__ uint32_t smem_u32(const void* p) {
    uint32_t a;
    asm("{ .reg .u64 t; cvta.to.shared.u64 t, %1; cvt.u32.u64 %0, t; }" : "=r"(a) : "l"(p));
    return a;
}
__device__ __forceinline__ void ldsm_x4(uint32_t r[4], uint32_t addr) {
    asm volatile("ldmatrix.sync.aligned.m8n8.x4.shared.b16 {%0,%1,%2,%3}, [%4];"
                 : "=r"(r[0]), "=r"(r[1]), "=r"(r[2]), "=r"(r[3]) : "r"(addr));
}
__device__ __forceinline__ void ldsm_x4_t(uint32_t r[4], uint32_t addr) {
    asm volatile("ldmatrix.sync.aligned.m8n8.x4.trans.shared.b16 {%0,%1,%2,%3}, [%4];"
                 : "=r"(r[0]), "=r"(r[1]), "=r"(r[2]), "=r"(r[3]) : "r"(addr));
}

// ---------------------------------------------------------------------------
// TF32 tensor-core GEMM (NT). SPLIT=1 writes bf16 hi/lo, SPLIT=0 writes fp32.
// ---------------------------------------------------------------------------
#define BM   128
#define BN   128
#define BKG  16
#define SST  136

template<int SPLIT>
__global__ __launch_bounds__(256, 2)
void gemm_tf32(const float* __restrict__ A, const float* __restrict__ W,
               float* __restrict__ C, __nv_bfloat16* __restrict__ Xh,
               __nv_bfloat16* __restrict__ Xl, int M, int N, int K)
{
    __shared__ unsigned As[BKG][SST];
    __shared__ unsigned Bs[BKG][SST];

    const int t    = threadIdx.x;
    const int lane = t & 31;
    const int wid  = t >> 5;
    const int wm   = (wid & 1) * 64;
    const int wn   = (wid >> 1) * 32;
    const int row0 = blockIdx.y * BM;
    const int col0 = blockIdx.x * BN;

    const int lm  = t >> 2;
    const int lkv = (t & 3) << 2;

    float acc[4][4][4];
#pragma unroll
    for (int i = 0; i < 4; i++)
#pragma unroll
        for (int j = 0; j < 4; j++)
#pragma unroll
            for (int r = 0; r < 4; r++) acc[i][j][r] = 0.0f;

    const int lq = lane & 3;
    const int lg = lane >> 2;

    float4 pa[2], pb[2];
#pragma unroll
    for (int it = 0; it < 2; it++) {
        pa[it] = *(const float4*)&A[(size_t)(row0 + lm + it * 64) * K + lkv];
        pb[it] = *(const float4*)&W[(size_t)(col0 + lm + it * 64) * K + lkv];
    }

    for (int k0 = 0; k0 < K; k0 += BKG) {
#pragma unroll
        for (int it = 0; it < 2; it++) {
            int m = lm + it * 64;
            As[lkv + 0][m] = f2tf32(pa[it].x);
            As[lkv + 1][m] = f2tf32(pa[it].y);
            As[lkv + 2][m] = f2tf32(pa[it].z);
            As[lkv + 3][m] = f2tf32(pa[it].w);
            Bs[lkv + 0][m] = f2tf32(pb[it].x);
            Bs[lkv + 1][m] = f2tf32(pb[it].y);
            Bs[lkv + 2][m] = f2tf32(pb[it].z);
            Bs[lkv + 3][m] = f2tf32(pb[it].w);
        }
        __syncthreads();

        if (k0 + BKG < K) {
#pragma unroll
            for (int it = 0; it < 2; it++) {
                pa[it] = *(const float4*)&A[(size_t)(row0 + lm + it * 64) * K + k0 + BKG + lkv];
                pb[it] = *(const float4*)&W[(size_t)(col0 + lm + it * 64) * K + k0 + BKG + lkv];
            }
        }

#pragma unroll
        for (int ks = 0; ks < 2; ks++) {
            const int kb = ks * 8;
            unsigned af[4][4], bf[4][2];
#pragma unroll
            for (int mi = 0; mi < 4; mi++) {
                const int mb = wm + mi * 16 + lg;
                af[mi][0] = As[kb + lq][mb];
                af[mi][1] = As[kb + lq][mb + 8];
                af[mi][2] = As[kb + 4 + lq][mb];
                af[mi][3] = As[kb + 4 + lq][mb + 8];
            }
#pragma unroll
            for (int ni = 0; ni < 4; ni++) {
                const int nb = wn + ni * 8 + lg;
                bf[ni][0] = Bs[kb + lq][nb];
                bf[ni][1] = Bs[kb + 4 + lq][nb];
            }
#pragma unroll
            for (int mi = 0; mi < 4; mi++)
#pragma unroll
                for (int ni = 0; ni < 4; ni++)
                    mma_tf32(acc[mi][ni], af[mi], bf[ni]);
        }
        __syncthreads();
    }

#pragma unroll
    for (int mi = 0; mi < 4; mi++) {
        const int r0 = row0 + wm + mi * 16 + lg;
#pragma unroll
        for (int ni = 0; ni < 4; ni++) {
            const int c0 = col0 + wn + ni * 8 + lq * 2;
            if (SPLIT) {
                uint32_t h0, l0, h1, l1;
                split2(acc[mi][ni][0], acc[mi][ni][1], h0, l0);
                split2(acc[mi][ni][2], acc[mi][ni][3], h1, l1);
                *(uint32_t*)&Xh[(size_t)r0 * N + c0]       = h0;
                *(uint32_t*)&Xl[(size_t)r0 * N + c0]       = l0;
                *(uint32_t*)&Xh[(size_t)(r0 + 8) * N + c0] = h1;
                *(uint32_t*)&Xl[(size_t)(r0 + 8) * N + c0] = l1;
            } else {
                *(float2*)&C[(size_t)r0 * N + c0]       = make_float2(acc[mi][ni][0], acc[mi][ni][1]);
                *(float2*)&C[(size_t)(r0 + 8) * N + c0] = make_float2(acc[mi][ni][2], acc[mi][ni][3]);
            }
        }
    }
}

// ---------------------------------------------------------------------------
// Causal flash attention, bf16x3 mma + ldmatrix fragments.
// Block 128 thr (4 warps), q-tile 64 (16 rows/warp), k-tiles of 64.
// smem: Kh/Kl/Vh/Vl all row-major [key][d], row stride 72 halves (144 B).
// Score B-frags: ldmatrix (no trans). PV B-frags: ldmatrix.trans on V[key][d].
// ---------------------------------------------------------------------------
#define KP   72
#define TSH  (64*KP)        // tile size in halves
#define RB   144            // row stride bytes
#define TSB  (64*RB)        // tile size bytes = 9216

__global__ __launch_bounds__(128, 3)
void attn_mma(const __nv_bfloat16* __restrict__ Qhg, const __nv_bfloat16* __restrict__ Qlg,
              const __nv_bfloat16* __restrict__ Khg, const __nv_bfloat16* __restrict__ Klg,
              const __nv_bfloat16* __restrict__ Vhg, const __nv_bfloat16* __restrict__ Vlg,
              float* __restrict__ CTX)
{
    __shared__ __align__(16) unsigned short sm[4 * TSH];

    const int tid  = threadIdx.x;
    const int lane = tid & 31;
    const int w    = tid >> 5;
    const int g    = lane >> 2;
    const int t4   = lane & 3;
    const int qt   = blockIdx.x;
    const int h    = blockIdx.y;
    const int b    = blockIdx.z;
    const int r_lo = qt * 64 + w * 16 + g;
    const int r_hi = r_lo + 8;
    const int hoff = h * DKH;

    const uint32_t sb  = smem_u32(sm);
    const uint32_t Kh0 = sb, Kl0 = sb + TSB, Vh0 = sb + 2 * TSB, Vl0 = sb + 3 * TSB;
    const uint32_t lkK = (uint32_t)((lane & 7) * RB + (lane >> 3) * 16);
    const uint32_t lkV = (uint32_t)(lane * RB);

    // Q fragments (hi/lo) from pre-split gmem
    uint32_t qh[4][4], ql[4][4];
#pragma unroll
    for (int c = 0; c < 4; c++) {
        const size_t plo = (size_t)(b * SS + r_lo) * DD + hoff + c * 16 + 2 * t4;
        const size_t phi = (size_t)(b * SS + r_hi) * DD + hoff + c * 16 + 2 * t4;
        qh[c][0] = *(const uint32_t*)&Qhg[plo];
        qh[c][1] = *(const uint32_t*)&Qhg[phi];
        qh[c][2] = *(const uint32_t*)&Qhg[plo + 8];
        qh[c][3] = *(const uint32_t*)&Qhg[phi + 8];
        ql[c][0] = *(const uint32_t*)&Qlg[plo];
        ql[c][1] = *(const uint32_t*)&Qlg[phi];
        ql[c][2] = *(const uint32_t*)&Qlg[plo + 8];
        ql[c][3] = *(const uint32_t*)&Qlg[phi + 8];
    }

    float o[8][4];
#pragma unroll
    for (int j = 0; j < 8; j++)
#pragma unroll
        for (int e = 0; e < 4; e++) o[j][e] = 0.0f;
    float m_lo = -1e30f, m_hi = -1e30f;
    float l_lo = 0.0f,  l_hi = 0.0f;

    for (int kt = 0; kt <= qt; kt++) {
        const int k0 = kt * 64;
        __syncthreads();
        // simple aligned bf16 tile copies (no cvt, no transpose)
        {
            const size_t gbase = (size_t)(b * SS + k0) * DD + hoff;
#pragma unroll
            for (int i = 0; i < 4; i++) {
                int idx = tid + i * 128;         // 0..511
                int r   = idx >> 3;              // 0..63
                int c8  = (idx & 7) << 3;        // 0..56 halves
                size_t go = gbase + (size_t)r * DD + c8;
                int so = r * KP + c8;
                *(uint4*)&sm[0 * TSH + so] = *(const uint4*)&Khg[go];
                *(uint4*)&sm[1 * TSH + so] = *(const uint4*)&Klg[go];
                *(uint4*)&sm[2 * TSH + so] = *(const uint4*)&Vhg[go];
                *(uint4*)&sm[3 * TSH + so] = *(const uint4*)&Vlg[go];
            }
        }
        __syncthreads();

        // scores: S[16x64] = Q @ K^T (bf16x3), B-frags via ldmatrix
        float s[8][4];
#pragma unroll
        for (int j = 0; j < 8; j++) {
            s[j][0] = s[j][1] = s[j][2] = s[j][3] = 0.0f;
            const uint32_t aKh = Kh0 + j * (8 * RB) + lkK;
            const uint32_t aKl = Kl0 + j * (8 * RB) + lkK;
#pragma unroll
            for (int cp = 0; cp < 4; cp += 2) {
                uint32_t bh[4], bl[4];
                ldsm_x4(bh, aKh + cp * 32);
                ldsm_x4(bl, aKl + cp * 32);
                mma_bf16(s[j], qh[cp], bh[0], bh[1]);
                mma_bf16(s[j], qh[cp], bl[0], bl[1]);
                mma_bf16(s[j], ql[cp], bh[0], bh[1]);
                mma_bf16(s[j], qh[cp + 1], bh[2], bh[3]);
                mma_bf16(s[j], qh[cp + 1], bl[2], bl[3]);
                mma_bf16(s[j], ql[cp + 1], bh[2], bh[3]);
            }
        }

        // scale + causal mask (diagonal tile only)
        const bool diag = (kt == qt);
#pragma unroll
        for (int j = 0; j < 8; j++) {
            const int col = k0 + 8 * j + 2 * t4;
            s[j][0] *= 0.125f; s[j][1] *= 0.125f;
            s[j][2] *= 0.125f; s[j][3] *= 0.125f;
            if (diag) {
                if (col     > r_lo) s[j][0] = -1e30f;
                if (col + 1 > r_lo) s[j][1] = -1e30f;
                if (col     > r_hi) s[j][2] = -1e30f;
                if (col + 1 > r_hi) s[j][3] = -1e30f;
            }
        }

        // online softmax
        float mx_lo = -1e30f, mx_hi = -1e30f;
#pragma unroll
        for (int j = 0; j < 8; j++) {
            mx_lo = fmaxf(mx_lo, fmaxf(s[j][0], s[j][1]));
            mx_hi = fmaxf(mx_hi, fmaxf(s[j][2], s[j][3]));
        }
        mx_lo = fmaxf(mx_lo, __shfl_xor_sync(0xFFFFFFFF, mx_lo, 1));
        mx_lo = fmaxf(mx_lo, __shfl_xor_sync(0xFFFFFFFF, mx_lo, 2));
        mx_hi = fmaxf(mx_hi, __shfl_xor_sync(0xFFFFFFFF, mx_hi, 1));
        mx_hi = fmaxf(mx_hi, __shfl_xor_sync(0xFFFFFFFF, mx_hi, 2));

        const float mn_lo = fmaxf(m_lo, mx_lo);
        const float mn_hi = fmaxf(m_hi, mx_hi);
        const float cr_lo = __expf(m_lo - mn_lo);
        const float cr_hi = __expf(m_hi - mn_hi);
        m_lo = mn_lo; m_hi = mn_hi;
        l_lo *= cr_lo; l_hi *= cr_hi;
#pragma unroll
        for (int j = 0; j < 8; j++) {
            o[j][0] *= cr_lo; o[j][1] *= cr_lo;
            o[j][2] *= cr_hi; o[j][3] *= cr_hi;
        }

        uint32_t pah[4][4], pal[4][4];
#pragma unroll
        for (int j = 0; j < 8; j++) {
            float p0 = __expf(s[j][0] - m_lo);
            float p1 = __expf(s[j][1] - m_lo);
            float p2 = __expf(s[j][2] - m_hi);
            float p3 = __expf(s[j][3] - m_hi);
            l_lo += p0 + p1;
            l_hi += p2 + p3;
            uint32_t h01, l01, h23, l23;
            split2(p0, p1, h01, l01);
            split2(p2, p3, h23, l23);
            const int c = j >> 1;
            if ((j & 1) == 0) {
                pah[c][0] = h01; pah[c][1] = h23;
                pal[c][0] = l01; pal[c][1] = l23;
            } else {
                pah[c][2] = h01; pah[c][3] = h23;
                pal[c][2] = l01; pal[c][3] = l23;
            }
        }

        // O += P @ V (bf16x3); V row-major in smem, frags via ldmatrix.trans
#pragma unroll
        for (int j = 0; j < 8; j++) {
            const uint32_t aVh = Vh0 + lkV + j * 16;
            const uint32_t aVl = Vl0 + lkV + j * 16;
#pragma unroll
            for (int cp = 0; cp < 4; cp += 2) {
                uint32_t bh[4], bl[4];
                ldsm_x4_t(bh, aVh + cp * (16 * RB));
                ldsm_x4_t(bl, aVl + cp * (16 * RB));
                mma_bf16(o[j], pah[cp], bh[0], bh[1]);
                mma_bf16(o[j], pah[cp], bl[0], bl[1]);
                mma_bf16(o[j], pal[cp], bh[0], bh[1]);
                mma_bf16(o[j], pah[cp + 1], bh[2], bh[3]);
                mma_bf16(o[j], pah[cp + 1], bl[2], bl[3]);
                mma_bf16(o[j], pal[cp + 1], bh[2], bh[3]);
            }
        }
    }

    l_lo += __shfl_xor_sync(0xFFFFFFFF, l_lo, 1);
    l_lo += __shfl_xor_sync(0xFFFFFFFF, l_lo, 2);
    l_hi += __shfl_xor_sync(0xFFFFFFFF, l_hi, 1);
    l_hi += __shfl_xor_sync(0xFFFFFFFF, l_hi, 2);
    const float inv_lo = 1.0f / l_lo;
    const float inv_hi = 1.0f / l_hi;

#pragma unroll
    for (int j = 0; j < 8; j++) {
        const int col = hoff + 8 * j + 2 * t4;
        *(float2*)&CTX[(size_t)(b * SS + r_lo) * DD + col] =
            make_float2(o[j][0] * inv_lo, o[j][1] * inv_lo);
        *(float2*)&CTX[(size_t)(b * SS + r_hi) * DD + col] =
            make_float2(o[j][2] * inv_hi, o[j][3] * inv_hi);
    }
}

// ---------------------------------------------------------------------------
// Launch
// ---------------------------------------------------------------------------
extern "C" void kernel_launch(void* const* d_in, const int* in_sizes, int n_in,
                              void* d_out, int out_size)
{
    const float* x  = (const float*)d_in[0];
    const float* Wq = (const float*)d_in[1];
    const float* Wk = (const float*)d_in[2];
    const float* Wv = (const float*)d_in[3];
    const float* Wo = (const float*)d_in[4];
    float* out = (float*)d_out;

    __nv_bfloat16 *qh, *ql, *kh, *kl, *vh, *vl;
    float* Cb;
    cudaGetSymbolAddress((void**)&qh, g_qh);
    cudaGetSymbolAddress((void**)&ql, g_ql);
    cudaGetSymbolAddress((void**)&kh, g_kh);
    cudaGetSymbolAddress((void**)&kl, g_kl);
    cudaGetSymbolAddress((void**)&vh, g_vh);
    cudaGetSymbolAddress((void**)&vl, g_vl);
    cudaGetSymbolAddress((void**)&Cb, g_C);

    dim3 gg(DD / BN, MM / BM);   // (8, 64)
    gemm_tf32<1><<<gg, 256>>>(x, Wq, nullptr, qh, ql, MM, DD, DD);
    gemm_tf32<1><<<gg, 256>>>(x, Wk, nullptr, kh, kl, MM, DD, DD);
    gemm_tf32<1><<<gg, 256>>>(x, Wv, nullptr, vh, vl, MM, DD, DD);

    dim3 ga(SS / 64, HH, BB);    // (32, 16, 4)
    attn_mma<<<ga, 128>>>(qh, ql, kh, kl, vh, vl, Cb);

    gemm_tf32<0><<<gg, 256>>>(Cb, Wo, out, nullptr, nullptr, MM, DD, DD);
}